// round 3
// baseline (speedup 1.0000x reference)
#include <cuda_runtime.h>

#define N_NODES 16384
#define DEG 16
#define H 128
#define G4 512           // 4*H
#define NPC 64           // nodes per CTA
#define KT 32            // k-tile
#define NT 256           // threads per CTA

// Pre-transposed weights: g_WT[s][k][col] = W[col*H + k], s=0 -> W_ih, s=1 -> W_hh
__device__ float g_WT[2][H][G4];

__global__ void transpose_w_kernel(const float* __restrict__ Wih,
                                   const float* __restrict__ Whh) {
    int idx = blockIdx.x * blockDim.x + threadIdx.x;
    if (idx < G4 * H) {
        int col = idx / H, k = idx % H;
        g_WT[0][k][col] = Wih[idx];
        g_WT[1][k][col] = Whh[idx];
    }
}

__device__ __forceinline__ float sigmoidf_fast(float v) {
    return 1.0f / (1.0f + __expf(-v));
}
__device__ __forceinline__ float lo_f32(unsigned long long v) {
    return __int_as_float((int)(unsigned int)v);
}
__device__ __forceinline__ float hi_f32(unsigned long long v) {
    return __int_as_float((int)(v >> 32));
}

__global__ __launch_bounds__(NT, 1)
void lstm_agg_kernel(const float* __restrict__ x,
                     const float* __restrict__ b_ih,
                     const float* __restrict__ b_hh,
                     float* __restrict__ out) {
    extern __shared__ float sm[];
    float* sh_x = sm;                  // NPC*H
    float* sh_h = sh_x + NPC * H;      // NPC*H
    float* sh_c = sh_h + NPC * H;      // NPC*H
    float* wt   = sh_c + NPC * H;      // KT*G4
    float* bias = wt + KT * G4;        // G4

    const int tid  = threadIdx.x;
    const int tx   = tid & 31;         // column group 0..31
    const int ty   = tid >> 5;         // row group 0..7
    const int row0 = ty * 8;
    const int colq = tx * 4;           // base col within a gate (0..127, step 4)
    const int n0   = blockIdx.x * NPC;

    for (int i = tid; i < G4; i += NT) bias[i] = b_ih[i] + b_hh[i];
    for (int i = tid; i < NPC * H; i += NT) { sh_h[i] = 0.0f; sh_c[i] = 0.0f; }
    __syncthreads();

    #pragma unroll 1
    for (int t = 0; t < DEG; ++t) {
        // ---- load x_t tile: 64 rows x 128 (prev-step reads of sh_x fenced by sync C) ----
        #pragma unroll
        for (int j = tid; j < NPC * H / 4; j += NT) {
            int m  = j >> 5;           // j / 32
            int k4 = j & 31;           // j % 32
            ((float4*)sh_x)[j] =
                *(const float4*)(x + ((size_t)(n0 + m) * DEG + t) * H + k4 * 4);
        }

        // ---- init accumulators with bias (f32x2 pairs) ----
        // acc2[r][g*2+p] holds gate cols (g*128 + colq + 2p, +2p+1) for row row0+r
        unsigned long long acc2[8][8];
        #pragma unroll
        for (int g = 0; g < 4; ++g) {
            ulonglong2 bb = *(const ulonglong2*)(bias + g * 128 + colq);
            #pragma unroll
            for (int r = 0; r < 8; ++r) {
                acc2[r][g * 2]     = bb.x;
                acc2[r][g * 2 + 1] = bb.y;
            }
        }

        // ---- GEMM: acc += src(64x128) @ WT(128x512), src = x_t then h ----
        #pragma unroll 1
        for (int s = 0; s < 2; ++s) {
            const float* src = (s == 0) ? sh_x : sh_h;
            #pragma unroll 1
            for (int kc = 0; kc < H; kc += KT) {
                __syncthreads();   // wt free; (first tile) sh_x ready / prev-step h-writes done
                // stage weight tile KT x G4 (contiguous in g_WT) -> smem
                const float4* wsrc = (const float4*)(&g_WT[s][kc][0]);
                #pragma unroll
                for (int j = 0; j < (KT * G4 / 4) / NT; ++j)
                    ((float4*)wt)[tid + j * NT] = wsrc[tid + j * NT];
                __syncthreads();

                #pragma unroll 2
                for (int kk4 = 0; kk4 < KT; kk4 += 4) {
                    float4 a4[8];
                    #pragma unroll
                    for (int r = 0; r < 8; ++r)
                        a4[r] = *(const float4*)(src + (row0 + r) * H + kc + kk4);
                    #pragma unroll
                    for (int u = 0; u < 4; ++u) {
                        unsigned long long b2[8];
                        #pragma unroll
                        for (int g = 0; g < 4; ++g) {
                            ulonglong2 bb = *(const ulonglong2*)(wt + (kk4 + u) * G4 + g * 128 + colq);
                            b2[g * 2]     = bb.x;
                            b2[g * 2 + 1] = bb.y;
                        }
                        #pragma unroll
                        for (int r = 0; r < 8; ++r) {
                            float av = (u == 0) ? a4[r].x : (u == 1) ? a4[r].y
                                     : (u == 2) ? a4[r].z : a4[r].w;
                            unsigned long long a2;
                            asm("mov.b64 %0, {%1, %1};" : "=l"(a2) : "f"(av));
                            #pragma unroll
                            for (int q = 0; q < 8; ++q)
                                asm("fma.rn.f32x2 %0, %1, %2, %0;"
                                    : "+l"(acc2[r][q]) : "l"(a2), "l"(b2[q]));
                        }
                    }
                }
            }
        }
        __syncthreads();   // sync C: all GEMM reads of sh_h/sh_x done before pointwise writes

        // ---- pointwise LSTM cell update ----
        #pragma unroll
        for (int r = 0; r < 8; ++r) {
            int m = row0 + r;
            float4 cold = *(const float4*)(sh_c + m * H + colq);
            float cn[4], hn[4];
            #pragma unroll
            for (int q = 0; q < 4; ++q) {
                // gate value for gate g at offset q: acc2[r][g*2 + q/2], lane q%2
                unsigned long long vi = acc2[r][0 + (q >> 1)];
                unsigned long long vf = acc2[r][2 + (q >> 1)];
                unsigned long long vg = acc2[r][4 + (q >> 1)];
                unsigned long long vo = acc2[r][6 + (q >> 1)];
                float gi = (q & 1) ? hi_f32(vi) : lo_f32(vi);
                float gf = (q & 1) ? hi_f32(vf) : lo_f32(vf);
                float gg = (q & 1) ? hi_f32(vg) : lo_f32(vg);
                float go = (q & 1) ? hi_f32(vo) : lo_f32(vo);
                float iv = sigmoidf_fast(gi);
                float fv = sigmoidf_fast(gf);
                float gv = tanhf(gg);
                float ov = sigmoidf_fast(go);
                float cprev = (q == 0) ? cold.x : (q == 1) ? cold.y
                            : (q == 2) ? cold.z : cold.w;
                float cnew = fv * cprev + iv * gv;
                cn[q] = cnew;
                hn[q] = ov * tanhf(cnew);
            }
            *(float4*)(sh_c + m * H + colq) = make_float4(cn[0], cn[1], cn[2], cn[3]);
            *(float4*)(sh_h + m * H + colq) = make_float4(hn[0], hn[1], hn[2], hn[3]);
        }
    }

    __syncthreads();
    // ---- write h_final for this node block ----
    #pragma unroll
    for (int j = tid; j < NPC * H / 4; j += NT) {
        ((float4*)(out + (size_t)n0 * H))[j] = ((const float4*)sh_h)[j];
    }
}

extern "C" void kernel_launch(void* const* d_in, const int* in_sizes, int n_in,
                              void* d_out, int out_size) {
    // metadata order: x, index, W_ih, W_hh, b_ih, b_hh, dim_size
    const float* x    = (const float*)d_in[0];
    const float* Wih  = (const float*)d_in[2];
    const float* Whh  = (const float*)d_in[3];
    const float* bih  = (const float*)d_in[4];
    const float* bhh  = (const float*)d_in[5];
    float* out = (float*)d_out;

    transpose_w_kernel<<<(G4 * H + 255) / 256, 256>>>(Wih, Whh);

    const int smem_bytes = (3 * NPC * H + KT * G4 + G4) * (int)sizeof(float);
    static bool attr_set = false;
    if (!attr_set) {
        cudaFuncSetAttribute(lstm_agg_kernel,
                             cudaFuncAttributeMaxDynamicSharedMemorySize, smem_bytes);
        attr_set = true;
    }
    lstm_agg_kernel<<<N_NODES / NPC, NT, smem_bytes>>>(x, bih, bhh, out);
}

// round 6
// speedup vs baseline: 2.8556x; 2.8556x over previous
#include <cuda_runtime.h>
#include <cuda_fp16.h>
#include <cstdint>

#define HD   128
#define NPC  64
#define NT   256
#define DEG  16
#define NNODES 16384

// Fragment-major weights: [mat(2: 0=ih,1=hh)][prec(2: 0=hi,1=lo)][mt(32)][kt(8)][lane(32)][8 halves]
// mt = w*4 + t4 encodes permuted gate rows: global row = t4*128 + w*16 + r_local.
__device__ __align__(16) __half g_Wfrag[2][2][32][8][32][8];

__global__ void prep_w(const float* __restrict__ Wih, const float* __restrict__ Whh) {
    int idx = blockIdx.x * blockDim.x + threadIdx.x;      // 16384 threads
    if (idx >= 2 * 32 * 8 * 32) return;
    int lane = idx & 31;
    int kt   = (idx >> 5) & 7;
    int mt   = (idx >> 8) & 31;
    int mat  = idx >> 13;
    const float* W = mat ? Whh : Wih;
    int w = mt >> 2, t4 = mt & 3;
    int g = lane >> 2, tig = lane & 3;
    int rb = t4 * 128 + w * 16;
    int kb = kt * 16 + tig * 2;
    // m16n8k16 A-fragment element order per lane:
    // (g,kb),(g,kb+1),(g+8,kb),(g+8,kb+1),(g,kb+8),(g,kb+9),(g+8,kb+8),(g+8,kb+9)
    int rows[8] = {g, g, g + 8, g + 8, g, g, g + 8, g + 8};
    int cols[8] = {kb, kb + 1, kb, kb + 1, kb + 8, kb + 9, kb + 8, kb + 9};
    __half hi[8], lo[8];
#pragma unroll
    for (int i = 0; i < 8; ++i) {
        float v = W[(rb + rows[i]) * HD + cols[i]];
        __half h = __float2half_rn(v);
        hi[i] = h;
        lo[i] = __float2half_rn(v - __half2float(h));
    }
    *(uint4*)&g_Wfrag[mat][0][mt][kt][lane][0] = *(uint4*)hi;
    *(uint4*)&g_Wfrag[mat][1][mt][kt][lane][0] = *(uint4*)lo;
}

__device__ __forceinline__ float sigf(float v) {
    return __fdividef(1.0f, 1.0f + __expf(-v));
}
__device__ __forceinline__ float tanh_f(float v) {
    return 1.0f - __fdividef(2.0f, 1.0f + __expf(2.0f * v));
}

#define MMA(acc, a, b0, b1)                                              \
    asm volatile("mma.sync.aligned.m16n8k16.row.col.f32.f16.f16.f32 "    \
                 "{%0,%1,%2,%3}, {%4,%5,%6,%7}, {%8,%9}, {%0,%1,%2,%3};" \
                 : "+f"((acc)[0]), "+f"((acc)[1]), "+f"((acc)[2]), "+f"((acc)[3]) \
                 : "r"((a).x), "r"((a).y), "r"((a).z), "r"((a).w), "r"(b0), "r"(b1))

// smem: HI[src(2)][kpair(64)][72 words], then LO same. 72 = 64 nodes + 8 pad (conflict-free).
#define ROWW 72
#define SMEM_WORDS (2 * 2 * 64 * ROWW)

__global__ __launch_bounds__(NT, 1)
void lstm_mma_kernel(const float* __restrict__ x,
                     const float* __restrict__ bih,
                     const float* __restrict__ bhh,
                     float* __restrict__ out) {
    extern __shared__ uint32_t sm[];
    uint32_t* HI = sm;
    uint32_t* LO = sm + 2 * 64 * ROWW;

    const int tid = threadIdx.x, lane = tid & 31, w = tid >> 5;
    const int g = lane >> 2, tig = lane & 3;
    const int n0 = blockIdx.x * NPC;

    // per-thread bias regs [gate-type][row-half]
    float bias[4][2];
#pragma unroll
    for (int t = 0; t < 4; ++t)
#pragma unroll
        for (int h = 0; h < 2; ++h) {
            int d = t * 128 + w * 16 + h * 8 + g;
            bias[t][h] = bih[d] + bhh[d];
        }

    float cst[8][2][2];                                     // c state [nt][half][cb]
#pragma unroll
    for (int a = 0; a < 8; ++a)
        for (int b = 0; b < 2; ++b)
            for (int c = 0; c < 2; ++c) cst[a][b][c] = 0.0f;

    // convert x(0) into src=0 slab
    {
        const int node = tid >> 2, dch = (tid & 3) * 32;
        const float* xr = x + ((size_t)(n0 + node) * DEG + 0) * HD + dch;
#pragma unroll
        for (int i = 0; i < 16; ++i) {
            float2 v = *(const float2*)(xr + 2 * i);
            float v0 = (v.x == v.x) ? v.x : 0.0f;
            float v1 = (v.y == v.y) ? v.y : 0.0f;
            __half2 h2 = __floats2half2_rn(v0, v1);
            __half2 l2 = __floats2half2_rn(v0 - __half2float(__low2half(h2)),
                                           v1 - __half2float(__high2half(h2)));
            int kp = (dch >> 1) + i;
            HI[kp * ROWW + node] = *(uint32_t*)&h2;
            LO[kp * ROWW + node] = *(uint32_t*)&l2;
        }
    }
    __syncthreads();

    float acc[4][8][4];

#pragma unroll 1
    for (int u = 0; u < DEG; ++u) {
#pragma unroll
        for (int t = 0; t < 4; ++t)
#pragma unroll
            for (int n = 0; n < 8; ++n)
#pragma unroll
                for (int r = 0; r < 4; ++r) acc[t][n][r] = 0.0f;

        // ---- GEMM: src 0 = x (Wih), src 1 = h (Whh) ----
#pragma unroll 1
        for (int src = 0; src < 2; ++src) {
            if (src == 1 && u == 0) break;
#pragma unroll 1
            for (int kt = 0; kt < 8; ++kt) {
                const int bidx = (src * 64 + kt * 8 + tig) * ROWW + g;
                uint4 af[4];
#pragma unroll
                for (int t = 0; t < 4; ++t)
                    af[t] = __ldg((const uint4*)&g_Wfrag[src][0][w * 4 + t][kt][lane][0]);
#pragma unroll
                for (int nt = 0; nt < 8; ++nt) {
                    uint32_t bh0 = HI[bidx + nt * 8];
                    uint32_t bh1 = HI[bidx + 4 * ROWW + nt * 8];
                    uint32_t bl0 = LO[bidx + nt * 8];
                    uint32_t bl1 = LO[bidx + 4 * ROWW + nt * 8];
#pragma unroll
                    for (int t = 0; t < 4; ++t) MMA(acc[t][nt], af[t], bh0, bh1);
#pragma unroll
                    for (int t = 0; t < 4; ++t) MMA(acc[t][nt], af[t], bl0, bl1);
                }
#pragma unroll
                for (int t = 0; t < 4; ++t)
                    af[t] = __ldg((const uint4*)&g_Wfrag[src][1][w * 4 + t][kt][lane][0]);
#pragma unroll
                for (int nt = 0; nt < 8; ++nt) {
                    uint32_t bh0 = HI[bidx + nt * 8];
                    uint32_t bh1 = HI[bidx + 4 * ROWW + nt * 8];
#pragma unroll
                    for (int t = 0; t < 4; ++t) MMA(acc[t][nt], af[t], bh0, bh1);
                }
            }
        }
        __syncthreads();   // all slab reads done before epilogue/convert writes

        // ---- epilogue: cell update ----
#pragma unroll
        for (int nt = 0; nt < 8; ++nt)
#pragma unroll
            for (int hf = 0; hf < 2; ++hf)
#pragma unroll
                for (int cb = 0; cb < 2; ++cb) {
                    const int ri = hf * 2 + cb;
                    float gi = acc[0][nt][ri] + bias[0][hf];
                    float gf = acc[1][nt][ri] + bias[1][hf];
                    float gg = acc[2][nt][ri] + bias[2][hf];
                    float go = acc[3][nt][ri] + bias[3][hf];
                    float iv = sigf(gi), fv = sigf(gf), gv = tanh_f(gg), ov = sigf(go);
                    float cn = fv * cst[nt][hf][cb] + iv * gv;
                    cst[nt][hf][cb] = cn;
                    float hv = ov * tanh_f(cn);
                    const int d = w * 16 + hf * 8 + g;
                    const int n = nt * 8 + tig * 2 + cb;
                    if (u < DEG - 1) {
                        __half hh = __float2half_rn(hv);
                        __half hl = __float2half_rn(hv - __half2float(hh));
                        const int kp = 64 + (d >> 1);   // src=1 slab
                        ((__half*)&HI[kp * ROWW + n])[d & 1] = hh;
                        ((__half*)&LO[kp * ROWW + n])[d & 1] = hl;
                    } else {
                        out[(size_t)(n0 + n) * HD + d] = hv;
                    }
                }

        // ---- convert x(u+1) ----
        if (u < DEG - 1) {
            const int node = tid >> 2, dch = (tid & 3) * 32;
            const float* xr = x + ((size_t)(n0 + node) * DEG + (u + 1)) * HD + dch;
#pragma unroll
            for (int i = 0; i < 16; ++i) {
                float2 v = *(const float2*)(xr + 2 * i);
                float v0 = (v.x == v.x) ? v.x : 0.0f;
                float v1 = (v.y == v.y) ? v.y : 0.0f;
                __half2 h2 = __floats2half2_rn(v0, v1);
                __half2 l2 = __floats2half2_rn(v0 - __half2float(__low2half(h2)),
                                               v1 - __half2float(__high2half(h2)));
                int kp = (dch >> 1) + i;
                HI[kp * ROWW + node] = *(uint32_t*)&h2;
                LO[kp * ROWW + node] = *(uint32_t*)&l2;
            }
        }
        __syncthreads();   // writes visible before next step's GEMM
    }
}

extern "C" void kernel_launch(void* const* d_in, const int* in_sizes, int n_in,
                              void* d_out, int out_size) {
    // metadata order: x, index, W_ih, W_hh, b_ih, b_hh, dim_size
    const float* x   = (const float*)d_in[0];
    const float* Wih = (const float*)d_in[2];
    const float* Whh = (const float*)d_in[3];
    const float* bih = (const float*)d_in[4];
    const float* bhh = (const float*)d_in[5];
    float* out = (float*)d_out;

    prep_w<<<64, 256>>>(Wih, Whh);

    const int smem_bytes = SMEM_WORDS * (int)sizeof(uint32_t);   // 73728
    static bool attr_set = false;
    if (!attr_set) {
        cudaFuncSetAttribute(lstm_mma_kernel,
                             cudaFuncAttributeMaxDynamicSharedMemorySize, smem_bytes);
        attr_set = true;
    }
    lstm_mma_kernel<<<NNODES / NPC, NT, smem_bytes>>>(x, bih, bhh, out);
}